// round 16
// baseline (speedup 1.0000x reference)
#include <cuda_runtime.h>
#include <cuda_bf16.h>

#define NNODES 100000
#define NEDGES 1600000
#define INDIM  1433
#define HID    50
#define OUTD   7
#define KCHUNKS 45     // ceil(1433/32)

// ---------------- scratch (static device memory; zero-initialized at load) ----
__device__ int   g_counts[NNODES];        // re-zeroed by scan_add for next replay
__device__ int   g_rowptr[NNODES + 1];
__device__ int   g_cursor[NNODES];
__device__ int   g_bsums[128];
__device__ int2  g_edge[NEDGES];          // {src, bits(dinv[src])}
__device__ float g_dinv[NNODES];
__device__ __nv_bfloat16 g_h1b[NNODES * 64];  // layer-1 linear out, bf16 (pad cols stay 0)
__device__ float g_z[NNODES * 8];             // layer-2 linear out (col 7 stays 0)
__device__ float g_w1p[KCHUNKS * 2048];       // W1 pre-padded: [45][32][64]

// ---------------- ptx helpers ----------------
__device__ __forceinline__ void mma_tf32(float* c,
                                         unsigned a0, unsigned a1, unsigned a2, unsigned a3,
                                         unsigned b0, unsigned b1) {
    asm("mma.sync.aligned.m16n8k8.row.col.f32.tf32.tf32.f32 "
        "{%0,%1,%2,%3}, {%4,%5,%6,%7}, {%8,%9}, {%0,%1,%2,%3};"
        : "+f"(c[0]), "+f"(c[1]), "+f"(c[2]), "+f"(c[3])
        : "r"(a0), "r"(a1), "r"(a2), "r"(a3), "r"(b0), "r"(b1));
}

__device__ __forceinline__ void cp_async16(unsigned dst, const float4* src) {
    asm volatile("cp.async.cg.shared.global [%0], [%1], 16;" :: "r"(dst), "l"(src));
}
__device__ __forceinline__ void cp_commit() { asm volatile("cp.async.commit_group;"); }
__device__ __forceinline__ void cp_wait1() { asm volatile("cp.async.wait_group 1;"); }
__device__ __forceinline__ void cp_wait0() { asm volatile("cp.async.wait_group 0;"); }

// unpack uint4 (8 bf16) and accumulate with weight
__device__ __forceinline__ void acc_bf16x8(float* a, uint4 u, float wq) {
    float2 p0 = __bfloat1622float2(*(__nv_bfloat162*)&u.x);
    float2 p1 = __bfloat1622float2(*(__nv_bfloat162*)&u.y);
    float2 p2 = __bfloat1622float2(*(__nv_bfloat162*)&u.z);
    float2 p3 = __bfloat1622float2(*(__nv_bfloat162*)&u.w);
    a[0] = fmaf(wq, p0.x, a[0]);
    a[1] = fmaf(wq, p0.y, a[1]);
    a[2] = fmaf(wq, p1.x, a[2]);
    a[3] = fmaf(wq, p1.y, a[3]);
    a[4] = fmaf(wq, p2.x, a[4]);
    a[5] = fmaf(wq, p2.y, a[5]);
    a[6] = fmaf(wq, p3.x, a[6]);
    a[7] = fmaf(wq, p3.y, a[7]);
}

// ---------------- W1 pre-pad: [45][32][64], zero padding ----------------
__global__ void w1pad_kernel(const float* __restrict__ w1) {
    int i = blockIdx.x * 256 + threadIdx.x;
    if (i < KCHUNKS * 2048) {
        int kc = i >> 11, rem = i & 2047;
        int kk = rem >> 6, n = rem & 63;
        int k = kc * 32 + kk;
        g_w1p[i] = (k < INDIM && n < HID) ? __ldg(&w1[k * HID + n]) : 0.f;
    }
}

// ---------------- CSR build ----------------
__global__ void count_kernel(const int* __restrict__ col) {
    int i = blockIdx.x * blockDim.x + threadIdx.x;
    if (i < NEDGES) atomicAdd(&g_counts[__ldg(&col[i])], 1);
}

// local scan of counts + dinv computation (fused)
__global__ void scan_local_kernel() {
    __shared__ int ws[32];
    int tid = threadIdx.x;
    int i = blockIdx.x * 1024 + tid;
    int v = (i < NNODES) ? g_counts[i] : 0;
    if (i < NNODES) g_dinv[i] = rsqrtf((float)(v + 1));  // +1 self loop
    int x = v;
#pragma unroll
    for (int d = 1; d < 32; d <<= 1) {
        int y = __shfl_up_sync(0xffffffffu, x, d);
        if ((tid & 31) >= d) x += y;
    }
    if ((tid & 31) == 31) ws[tid >> 5] = x;
    __syncthreads();
    if (tid < 32) {
        int w = ws[tid];
#pragma unroll
        for (int d = 1; d < 32; d <<= 1) {
            int y = __shfl_up_sync(0xffffffffu, w, d);
            if (tid >= d) w += y;
        }
        ws[tid] = w;
    }
    __syncthreads();
    int woff = (tid >= 32) ? ws[(tid >> 5) - 1] : 0;
    int incl = x + woff;
    if (i < NNODES) g_rowptr[i] = incl - v;       // local exclusive
    if (tid == 1023) g_bsums[blockIdx.x] = incl;  // block total
}

__global__ void scan_bsums_kernel() {
    __shared__ int ws[4];
    int tid = threadIdx.x;
    int v = (tid < 98) ? g_bsums[tid] : 0;
    int x = v;
#pragma unroll
    for (int d = 1; d < 32; d <<= 1) {
        int y = __shfl_up_sync(0xffffffffu, x, d);
        if ((tid & 31) >= d) x += y;
    }
    if ((tid & 31) == 31) ws[tid >> 5] = x;
    __syncthreads();
    if (tid < 4) {
        int wv = ws[tid];
#pragma unroll
        for (int d = 1; d < 4; d <<= 1) {
            int y = __shfl_up_sync(0x0000000fu, wv, d);
            if (tid >= d) wv += y;
        }
        ws[tid] = wv;
    }
    __syncthreads();
    int off = (tid >= 32) ? ws[(tid >> 5) - 1] : 0;
    if (tid < 98) g_bsums[tid] = x + off - v;
}

__global__ void scan_add_kernel() {
    int i = blockIdx.x * blockDim.x + threadIdx.x;
    if (i < NNODES) {
        int val = g_rowptr[i] + g_bsums[i >> 10];
        g_rowptr[i] = val;
        g_cursor[i] = val;
        g_counts[i] = 0;  // reset for next graph replay
    }
    if (i == 0) g_rowptr[NNODES] = NEDGES;
}

__global__ void scatter_kernel(const int* __restrict__ row, const int* __restrict__ col) {
    int i = blockIdx.x * blockDim.x + threadIdx.x;
    if (i < NEDGES) {
        int c = __ldg(&col[i]);
        int r = __ldg(&row[i]);
        int p = atomicAdd(&g_cursor[c], 1);
        g_edge[p] = make_int2(r, __float_as_int(__ldg(&g_dinv[r])));
    }
}

// ---------------- GEMM1: h1 = x @ W1 (tf32 HMMA) — R4 champion, frozen -------
// A fragments loaded DIRECTLY from gmem (no smem roundtrip).
// B double-buffered in smem via cp.async 16B (from padded g_w1p).
// 128 threads = 4 warps; block tile M=128 (warp 32 rows), N=56, K chunk 32.
#define BLD 72   // Bs ld: frag bank = (8*tg+gid) mod 32 -> conflict-free

__global__ __launch_bounds__(128, 4) void gemm1_kernel(const float* __restrict__ x) {
    __shared__ float Bs[2][32 * BLD];
    int t = threadIdx.x, lane = t & 31, w = t >> 5;
    int gid = lane >> 2, tg = lane & 3;
    int mbase = blockIdx.x * 128;
    int rw = mbase + w * 32;

    unsigned bsb = (unsigned)__cvta_generic_to_shared(&Bs[0][0]);
    const float4* w1p4 = (const float4*)g_w1p;

    float acc[14][4];  // [mt*7+nt][j]
#pragma unroll
    for (int i = 0; i < 14; i++)
#pragma unroll
        for (int j = 0; j < 4; j++) acc[i][j] = 0.f;

    // per-thread A row pointers + validity (rows: rw + mt*16 + gid, +8)
    const float* xp[4];
    bool rok[4];
#pragma unroll
    for (int mt = 0; mt < 2; mt++) {
        int r0 = rw + mt * 16 + gid;
        int r1 = r0 + 8;
        rok[mt * 2]     = r0 < NNODES;
        rok[mt * 2 + 1] = r1 < NNODES;
        xp[mt * 2]      = x + (size_t)(rok[mt * 2] ? r0 : 0) * INDIM;
        xp[mt * 2 + 1]  = x + (size_t)(rok[mt * 2 + 1] ? r1 : 0) * INDIM;
    }

    auto stageB = [&](int kc, int buf) {
        unsigned bbase = bsb + buf * (32 * BLD * 4);
#pragma unroll
        for (int i = 0; i < 4; i++) {
            int idx = (t + i * 128) * 4;          // float index in [0,2048)
            int kk = idx >> 6, n = idx & 63;
            cp_async16(bbase + (kk * BLD + n) * 4, &w1p4[kc * 512 + t + i * 128]);
        }
        cp_commit();
    };

    stageB(0, 0);

    for (int kc = 0; kc < KCHUNKS; kc++) {
        int buf = kc & 1;
        int kb = kc * 32;

        // A fragments for this chunk: direct LDG (issued early, latency hidden
        // under B wait + sync + LDS below, and by desynchronized sibling CTAs)
        float aF[2][4][4];  // [mt][k8][j]
#pragma unroll
        for (int k8 = 0; k8 < 4; k8++) {
            int c0 = kb + k8 * 8 + tg;
            bool c0ok = c0 < INDIM;
            bool c1ok = (c0 + 4) < INDIM;
#pragma unroll
            for (int mt = 0; mt < 2; mt++) {
                aF[mt][k8][0] = (rok[mt * 2]     && c0ok) ? __ldg(xp[mt * 2] + c0)         : 0.f;
                aF[mt][k8][1] = (rok[mt * 2 + 1] && c0ok) ? __ldg(xp[mt * 2 + 1] + c0)     : 0.f;
                aF[mt][k8][2] = (rok[mt * 2]     && c1ok) ? __ldg(xp[mt * 2] + c0 + 4)     : 0.f;
                aF[mt][k8][3] = (rok[mt * 2 + 1] && c1ok) ? __ldg(xp[mt * 2 + 1] + c0 + 4) : 0.f;
            }
        }

        if (kc + 1 < KCHUNKS) { stageB(kc + 1, buf ^ 1); cp_wait1(); }
        else cp_wait0();
        __syncthreads();

        const float* B = &Bs[buf][0];
#pragma unroll
        for (int k8 = 0; k8 < 4; k8++) {
            int kk = k8 * 8;
            unsigned b0[7], b1[7];
#pragma unroll
            for (int nt = 0; nt < 7; nt++) {
                b0[nt] = __float_as_uint(B[(kk + tg) * BLD + nt * 8 + gid]);
                b1[nt] = __float_as_uint(B[(kk + tg + 4) * BLD + nt * 8 + gid]);
            }
#pragma unroll
            for (int mt = 0; mt < 2; mt++) {
#pragma unroll
                for (int nt = 0; nt < 7; nt++)
                    mma_tf32(acc[mt * 7 + nt],
                             __float_as_uint(aF[mt][k8][0]), __float_as_uint(aF[mt][k8][1]),
                             __float_as_uint(aF[mt][k8][2]), __float_as_uint(aF[mt][k8][3]),
                             b0[nt], b1[nt]);
            }
        }
        __syncthreads();  // Bs[buf] free before restage in next iteration
    }

    // epilogue: write bf16 pairs (c0 in {0,2,..,48})
    unsigned* hout = (unsigned*)g_h1b;
#pragma unroll
    for (int mt = 0; mt < 2; mt++) {
#pragma unroll
        for (int nt = 0; nt < 7; nt++) {
            int c0 = nt * 8 + tg * 2;
            if (c0 < HID) {
#pragma unroll
                for (int h = 0; h < 2; h++) {
                    int r = mbase + w * 32 + mt * 16 + gid + h * 8;
                    if (r < NNODES) {
                        __nv_bfloat162 bv = __float22bfloat162_rn(
                            make_float2(acc[mt * 7 + nt][h * 2], acc[mt * 7 + nt][h * 2 + 1]));
                        hout[(size_t)r * 32 + (c0 >> 1)] = *(unsigned*)&bv;
                    }
                }
            }
        }
    }
}

// ---------------- Aggregation 1 + fused lin2 (1 node per QUARTER-warp) -------
// 8 lanes per node; lane covers cols [8*l8, 8*l8+8) as one uint4 (8 bf16).
// lin2: smem transpose; lane jo (0..6) of each node computes output jo over
// all 64 cols. (champion form, unchanged)
__global__ __launch_bounds__(256) void agg1_kernel(const float* __restrict__ b1,
                                                   const float* __restrict__ w2) {
    __shared__ float w2s[64 * OUTD];   // zero-extended rows 50..63
    __shared__ float o1s[32][68];      // row stride 68 -> bank-conflict-free
    int t = threadIdx.x;
    int hw = t >> 3;        // node slot 0..31
    int l8 = t & 7;
    for (int i = t; i < 64 * OUTD; i += 256)
        w2s[i] = (i < HID * OUTD) ? __ldg(&w2[i]) : 0.f;
    __syncthreads();
    int v = blockIdx.x * 32 + hw;   // grid 3125 * 32 = 100000 exactly
    int s0 = __ldg(&g_rowptr[v]);
    int s1 = __ldg(&g_rowptr[v + 1]);
    float dv = __ldg(&g_dinv[v]);
    const uint4* hb = (const uint4*)g_h1b;   // 8 uint4 per row

    float a[8] = {0.f, 0.f, 0.f, 0.f, 0.f, 0.f, 0.f, 0.f};
    uint4 su = __ldg(&hb[(size_t)v * 8 + l8]);
    acc_bf16x8(a, su, dv);

    int j = s0;
    for (; j + 3 < s1; j += 4) {
        int2 e0 = __ldg(&g_edge[j]);
        int2 e1 = __ldg(&g_edge[j + 1]);
        int2 e2 = __ldg(&g_edge[j + 2]);
        int2 e3 = __ldg(&g_edge[j + 3]);
        uint4 u0 = __ldg(&hb[(size_t)e0.x * 8 + l8]);
        uint4 u1 = __ldg(&hb[(size_t)e1.x * 8 + l8]);
        uint4 u2 = __ldg(&hb[(size_t)e2.x * 8 + l8]);
        uint4 u3 = __ldg(&hb[(size_t)e3.x * 8 + l8]);
        acc_bf16x8(a, u0, __int_as_float(e0.y));
        acc_bf16x8(a, u1, __int_as_float(e1.y));
        acc_bf16x8(a, u2, __int_as_float(e2.y));
        acc_bf16x8(a, u3, __int_as_float(e3.y));
    }
    for (; j < s1; j++) {
        int2 e = __ldg(&g_edge[j]);
        uint4 u = __ldg(&hb[(size_t)e.x * 8 + l8]);
        acc_bf16x8(a, u, __int_as_float(e.y));
    }

    // relu + b1 for the 8 covered cols; pad cols (f >= HID) forced to 0
    float o[8];
#pragma unroll
    for (int c = 0; c < 8; c++) {
        int f = 8 * l8 + c;
        o[c] = (f < HID) ? fmaxf(fmaf(dv, a[c], __ldg(&b1[f])), 0.f) : 0.f;
    }
    *(float4*)&o1s[hw][8 * l8]     = make_float4(o[0], o[1], o[2], o[3]);
    *(float4*)&o1s[hw][8 * l8 + 4] = make_float4(o[4], o[5], o[6], o[7]);
    __syncwarp();

    // reduction: lane jo (=l8) computes output jo over all 64 columns
    if (l8 < 7) {
        float p = 0.f;
#pragma unroll
        for (int f = 0; f < 64; f++)
            p = fmaf(o1s[hw][f], w2s[f * OUTD + l8], p);
        g_z[(size_t)v * 8 + l8] = p;
    }
}

// ---------------- Aggregation 2 (+b2, sigmoid; 1 node per 4 lanes) -----------
// 4 lanes per node; lane covers z cols {2*l4, 2*l4+1} as one float2.
// 8 node streams per warp: per 4-edge iteration, 8 LDG warp-issues serve
// 32 node-edges (0.25 issues/edge, 2x gather MLP vs 8-lane form).
__global__ __launch_bounds__(256) void agg2_kernel(const float* __restrict__ b2,
                                                   float* __restrict__ out) {
    int t = threadIdx.x;
    int l4 = t & 3;
    int v = blockIdx.x * 64 + (t >> 2);
    if (v >= NNODES) return;
    int s0 = __ldg(&g_rowptr[v]);
    int s1 = __ldg(&g_rowptr[v + 1]);
    float dv = __ldg(&g_dinv[v]);
    const float2* zb = (const float2*)g_z;   // 4 float2 per row

    float2 acc;
    {
        float2 sz = __ldg(&zb[(size_t)v * 4 + l4]);
        acc = make_float2(dv * sz.x, dv * sz.y);
    }
    int j = s0;
    for (; j + 3 < s1; j += 4) {
        int2 e0 = __ldg(&g_edge[j]);
        int2 e1 = __ldg(&g_edge[j + 1]);
        int2 e2 = __ldg(&g_edge[j + 2]);
        int2 e3 = __ldg(&g_edge[j + 3]);
        float2 z0 = __ldg(&zb[(size_t)e0.x * 4 + l4]);
        float2 z1 = __ldg(&zb[(size_t)e1.x * 4 + l4]);
        float2 z2 = __ldg(&zb[(size_t)e2.x * 4 + l4]);
        float2 z3 = __ldg(&zb[(size_t)e3.x * 4 + l4]);
        float w0 = __int_as_float(e0.y), w1v = __int_as_float(e1.y);
        float w2v = __int_as_float(e2.y), w3 = __int_as_float(e3.y);
        acc.x = fmaf(w0, z0.x, acc.x);   acc.y = fmaf(w0, z0.y, acc.y);
        acc.x = fmaf(w1v, z1.x, acc.x);  acc.y = fmaf(w1v, z1.y, acc.y);
        acc.x = fmaf(w2v, z2.x, acc.x);  acc.y = fmaf(w2v, z2.y, acc.y);
        acc.x = fmaf(w3, z3.x, acc.x);   acc.y = fmaf(w3, z3.y, acc.y);
    }
    for (; j < s1; j++) {
        int2 e = __ldg(&g_edge[j]);
        float2 zv = __ldg(&zb[(size_t)e.x * 4 + l4]);
        float we = __int_as_float(e.y);
        acc.x = fmaf(we, zv.x, acc.x);
        acc.y = fmaf(we, zv.y, acc.y);
    }
    int c0 = 2 * l4, c1 = 2 * l4 + 1;
    if (c0 < OUTD) {
        float zz = fmaf(dv, acc.x, __ldg(&b2[c0]));
        out[v * OUTD + c0] = 1.f / (1.f + __expf(-zz));
    }
    if (c1 < OUTD) {
        float zz = fmaf(dv, acc.y, __ldg(&b2[c1]));
        out[v * OUTD + c1] = 1.f / (1.f + __expf(-zz));
    }
}

// ---------------- launch (two-stream fork/join for CSR || GEMM overlap) ------
struct AsyncRes {
    cudaStream_t s1;
    cudaEvent_t eFork, eJoin;
    AsyncRes() {
        cudaStreamCreateWithFlags(&s1, cudaStreamNonBlocking);
        cudaEventCreateWithFlags(&eFork, cudaEventDisableTiming);
        cudaEventCreateWithFlags(&eJoin, cudaEventDisableTiming);
    }
};

extern "C" void kernel_launch(void* const* d_in, const int* in_sizes, int n_in,
                              void* d_out, int out_size) {
    static AsyncRes ar;  // created on first (non-captured) correctness call

    const float* x  = (const float*)d_in[0];
    const int*   ei = (const int*)d_in[1];
    const float* w1 = (const float*)d_in[2];
    const float* b1 = (const float*)d_in[3];
    const float* w2 = (const float*)d_in[4];
    const float* b2 = (const float*)d_in[5];
    float* out = (float*)d_out;

    const int* row = ei;            // edge_index[0] = src
    const int* col = ei + NEDGES;   // edge_index[1] = dst

    // fork: CSR chain on s1, GEMM path on stream 0 — fully independent
    cudaEventRecord(ar.eFork, 0);
    cudaStreamWaitEvent(ar.s1, ar.eFork, 0);

    // stream 0: dense path
    w1pad_kernel<<<360, 256>>>(w1);
    gemm1_kernel<<<782, 128>>>(x);

    // stream s1: CSR build (hidden under gemm1)
    count_kernel<<<6250, 256, 0, ar.s1>>>(col);
    scan_local_kernel<<<98, 1024, 0, ar.s1>>>();      // also computes dinv
    scan_bsums_kernel<<<1, 128, 0, ar.s1>>>();
    scan_add_kernel<<<391, 256, 0, ar.s1>>>();        // also zeroes counts
    scatter_kernel<<<6250, 256, 0, ar.s1>>>(row, col);

    // join
    cudaEventRecord(ar.eJoin, ar.s1);
    cudaStreamWaitEvent(0, ar.eJoin, 0);

    // aggregations (need both paths)
    agg1_kernel<<<3125, 256>>>(b1, w2);               // fused lin2, 32 nodes/block
    agg2_kernel<<<1563, 256>>>(b2, out);              // 64 nodes/block
}

// round 17
// speedup vs baseline: 1.4017x; 1.4017x over previous
#include <cuda_runtime.h>
#include <cuda_bf16.h>

#define NNODES 100000
#define NEDGES 1600000
#define INDIM  1433
#define HID    50
#define OUTD   7
#define KCHUNKS 45     // ceil(1433/32)

// ---------------- scratch (static device memory; zero-initialized at load) ----
__device__ int   g_counts[NNODES];        // re-zeroed by scan_add for next replay
__device__ int   g_rowptr[NNODES + 1];
__device__ int   g_cursor[NNODES];
__device__ int   g_bsums[128];
__device__ int2  g_edge[NEDGES];          // {src, bits(dinv[src])}
__device__ float g_dinv[NNODES];
__device__ __nv_bfloat16 g_h1b[NNODES * 64];  // layer-1 linear out, bf16 (pad cols stay 0)
__device__ float g_z[NNODES * 8];             // layer-2 linear out (col 7 stays 0)
__device__ float g_w1p[KCHUNKS * 2048];       // W1 pre-padded: [45][32][64]

// ---------------- ptx helpers ----------------
__device__ __forceinline__ void mma_tf32(float* c,
                                         unsigned a0, unsigned a1, unsigned a2, unsigned a3,
                                         unsigned b0, unsigned b1) {
    asm("mma.sync.aligned.m16n8k8.row.col.f32.tf32.tf32.f32 "
        "{%0,%1,%2,%3}, {%4,%5,%6,%7}, {%8,%9}, {%0,%1,%2,%3};"
        : "+f"(c[0]), "+f"(c[1]), "+f"(c[2]), "+f"(c[3])
        : "r"(a0), "r"(a1), "r"(a2), "r"(a3), "r"(b0), "r"(b1));
}

__device__ __forceinline__ void cp_async16(unsigned dst, const float4* src) {
    asm volatile("cp.async.cg.shared.global [%0], [%1], 16;" :: "r"(dst), "l"(src));
}
__device__ __forceinline__ void cp_commit() { asm volatile("cp.async.commit_group;"); }
__device__ __forceinline__ void cp_wait1() { asm volatile("cp.async.wait_group 1;"); }
__device__ __forceinline__ void cp_wait0() { asm volatile("cp.async.wait_group 0;"); }

// unpack uint4 (8 bf16) and accumulate with weight
__device__ __forceinline__ void acc_bf16x8(float* a, uint4 u, float wq) {
    float2 p0 = __bfloat1622float2(*(__nv_bfloat162*)&u.x);
    float2 p1 = __bfloat1622float2(*(__nv_bfloat162*)&u.y);
    float2 p2 = __bfloat1622float2(*(__nv_bfloat162*)&u.z);
    float2 p3 = __bfloat1622float2(*(__nv_bfloat162*)&u.w);
    a[0] = fmaf(wq, p0.x, a[0]);
    a[1] = fmaf(wq, p0.y, a[1]);
    a[2] = fmaf(wq, p1.x, a[2]);
    a[3] = fmaf(wq, p1.y, a[3]);
    a[4] = fmaf(wq, p2.x, a[4]);
    a[5] = fmaf(wq, p2.y, a[5]);
    a[6] = fmaf(wq, p3.x, a[6]);
    a[7] = fmaf(wq, p3.y, a[7]);
}

// ---------------- W1 pre-pad: [45][32][64], zero padding ----------------
__global__ void w1pad_kernel(const float* __restrict__ w1) {
    int i = blockIdx.x * 256 + threadIdx.x;
    if (i < KCHUNKS * 2048) {
        int kc = i >> 11, rem = i & 2047;
        int kk = rem >> 6, n = rem & 63;
        int k = kc * 32 + kk;
        g_w1p[i] = (k < INDIM && n < HID) ? __ldg(&w1[k * HID + n]) : 0.f;
    }
}

// ---------------- CSR build ----------------
__global__ void count_kernel(const int* __restrict__ col) {
    int i = blockIdx.x * blockDim.x + threadIdx.x;
    if (i < NEDGES) atomicAdd(&g_counts[__ldg(&col[i])], 1);
}

// local scan of counts + dinv computation (fused)
__global__ void scan_local_kernel() {
    __shared__ int ws[32];
    int tid = threadIdx.x;
    int i = blockIdx.x * 1024 + tid;
    int v = (i < NNODES) ? g_counts[i] : 0;
    if (i < NNODES) g_dinv[i] = rsqrtf((float)(v + 1));  // +1 self loop
    int x = v;
#pragma unroll
    for (int d = 1; d < 32; d <<= 1) {
        int y = __shfl_up_sync(0xffffffffu, x, d);
        if ((tid & 31) >= d) x += y;
    }
    if ((tid & 31) == 31) ws[tid >> 5] = x;
    __syncthreads();
    if (tid < 32) {
        int w = ws[tid];
#pragma unroll
        for (int d = 1; d < 32; d <<= 1) {
            int y = __shfl_up_sync(0xffffffffu, w, d);
            if (tid >= d) w += y;
        }
        ws[tid] = w;
    }
    __syncthreads();
    int woff = (tid >= 32) ? ws[(tid >> 5) - 1] : 0;
    int incl = x + woff;
    if (i < NNODES) g_rowptr[i] = incl - v;       // local exclusive
    if (tid == 1023) g_bsums[blockIdx.x] = incl;  // block total
}

__global__ void scan_bsums_kernel() {
    __shared__ int ws[4];
    int tid = threadIdx.x;
    int v = (tid < 98) ? g_bsums[tid] : 0;
    int x = v;
#pragma unroll
    for (int d = 1; d < 32; d <<= 1) {
        int y = __shfl_up_sync(0xffffffffu, x, d);
        if ((tid & 31) >= d) x += y;
    }
    if ((tid & 31) == 31) ws[tid >> 5] = x;
    __syncthreads();
    if (tid < 4) {
        int wv = ws[tid];
#pragma unroll
        for (int d = 1; d < 4; d <<= 1) {
            int y = __shfl_up_sync(0x0000000fu, wv, d);
            if (tid >= d) wv += y;
        }
        ws[tid] = wv;
    }
    __syncthreads();
    int off = (tid >= 32) ? ws[(tid >> 5) - 1] : 0;
    if (tid < 98) g_bsums[tid] = x + off - v;
}

__global__ void scan_add_kernel() {
    int i = blockIdx.x * blockDim.x + threadIdx.x;
    if (i < NNODES) {
        int val = g_rowptr[i] + g_bsums[i >> 10];
        g_rowptr[i] = val;
        g_cursor[i] = val;
        g_counts[i] = 0;  // reset for next graph replay
    }
    if (i == 0) g_rowptr[NNODES] = NEDGES;
}

__global__ void scatter_kernel(const int* __restrict__ row, const int* __restrict__ col) {
    int i = blockIdx.x * blockDim.x + threadIdx.x;
    if (i < NEDGES) {
        int c = __ldg(&col[i]);
        int r = __ldg(&row[i]);
        int p = atomicAdd(&g_cursor[c], 1);
        g_edge[p] = make_int2(r, __float_as_int(__ldg(&g_dinv[r])));
    }
}

// ---------------- GEMM1: h1 = x @ W1 (tf32 HMMA) — R4 champion, frozen -------
// A fragments loaded DIRECTLY from gmem (no smem roundtrip).
// B double-buffered in smem via cp.async 16B (from padded g_w1p).
// 128 threads = 4 warps; block tile M=128 (warp 32 rows), N=56, K chunk 32.
#define BLD 72   // Bs ld: frag bank = (8*tg+gid) mod 32 -> conflict-free

__global__ __launch_bounds__(128, 4) void gemm1_kernel(const float* __restrict__ x) {
    __shared__ float Bs[2][32 * BLD];
    int t = threadIdx.x, lane = t & 31, w = t >> 5;
    int gid = lane >> 2, tg = lane & 3;
    int mbase = blockIdx.x * 128;
    int rw = mbase + w * 32;

    unsigned bsb = (unsigned)__cvta_generic_to_shared(&Bs[0][0]);
    const float4* w1p4 = (const float4*)g_w1p;

    float acc[14][4];  // [mt*7+nt][j]
#pragma unroll
    for (int i = 0; i < 14; i++)
#pragma unroll
        for (int j = 0; j < 4; j++) acc[i][j] = 0.f;

    // per-thread A row pointers + validity (rows: rw + mt*16 + gid, +8)
    const float* xp[4];
    bool rok[4];
#pragma unroll
    for (int mt = 0; mt < 2; mt++) {
        int r0 = rw + mt * 16 + gid;
        int r1 = r0 + 8;
        rok[mt * 2]     = r0 < NNODES;
        rok[mt * 2 + 1] = r1 < NNODES;
        xp[mt * 2]      = x + (size_t)(rok[mt * 2] ? r0 : 0) * INDIM;
        xp[mt * 2 + 1]  = x + (size_t)(rok[mt * 2 + 1] ? r1 : 0) * INDIM;
    }

    auto stageB = [&](int kc, int buf) {
        unsigned bbase = bsb + buf * (32 * BLD * 4);
#pragma unroll
        for (int i = 0; i < 4; i++) {
            int idx = (t + i * 128) * 4;          // float index in [0,2048)
            int kk = idx >> 6, n = idx & 63;
            cp_async16(bbase + (kk * BLD + n) * 4, &w1p4[kc * 512 + t + i * 128]);
        }
        cp_commit();
    };

    stageB(0, 0);

    for (int kc = 0; kc < KCHUNKS; kc++) {
        int buf = kc & 1;
        int kb = kc * 32;

        // A fragments for this chunk: direct LDG (issued early, latency hidden
        // under B wait + sync + LDS below, and by desynchronized sibling CTAs)
        float aF[2][4][4];  // [mt][k8][j]
#pragma unroll
        for (int k8 = 0; k8 < 4; k8++) {
            int c0 = kb + k8 * 8 + tg;
            bool c0ok = c0 < INDIM;
            bool c1ok = (c0 + 4) < INDIM;
#pragma unroll
            for (int mt = 0; mt < 2; mt++) {
                aF[mt][k8][0] = (rok[mt * 2]     && c0ok) ? __ldg(xp[mt * 2] + c0)         : 0.f;
                aF[mt][k8][1] = (rok[mt * 2 + 1] && c0ok) ? __ldg(xp[mt * 2 + 1] + c0)     : 0.f;
                aF[mt][k8][2] = (rok[mt * 2]     && c1ok) ? __ldg(xp[mt * 2] + c0 + 4)     : 0.f;
                aF[mt][k8][3] = (rok[mt * 2 + 1] && c1ok) ? __ldg(xp[mt * 2 + 1] + c0 + 4) : 0.f;
            }
        }

        if (kc + 1 < KCHUNKS) { stageB(kc + 1, buf ^ 1); cp_wait1(); }
        else cp_wait0();
        __syncthreads();

        const float* B = &Bs[buf][0];
#pragma unroll
        for (int k8 = 0; k8 < 4; k8++) {
            int kk = k8 * 8;
            unsigned b0[7], b1[7];
#pragma unroll
            for (int nt = 0; nt < 7; nt++) {
                b0[nt] = __float_as_uint(B[(kk + tg) * BLD + nt * 8 + gid]);
                b1[nt] = __float_as_uint(B[(kk + tg + 4) * BLD + nt * 8 + gid]);
            }
#pragma unroll
            for (int mt = 0; mt < 2; mt++) {
#pragma unroll
                for (int nt = 0; nt < 7; nt++)
                    mma_tf32(acc[mt * 7 + nt],
                             __float_as_uint(aF[mt][k8][0]), __float_as_uint(aF[mt][k8][1]),
                             __float_as_uint(aF[mt][k8][2]), __float_as_uint(aF[mt][k8][3]),
                             b0[nt], b1[nt]);
            }
        }
        __syncthreads();  // Bs[buf] free before restage in next iteration
    }

    // epilogue: write bf16 pairs (c0 in {0,2,..,48})
    unsigned* hout = (unsigned*)g_h1b;
#pragma unroll
    for (int mt = 0; mt < 2; mt++) {
#pragma unroll
        for (int nt = 0; nt < 7; nt++) {
            int c0 = nt * 8 + tg * 2;
            if (c0 < HID) {
#pragma unroll
                for (int h = 0; h < 2; h++) {
                    int r = mbase + w * 32 + mt * 16 + gid + h * 8;
                    if (r < NNODES) {
                        __nv_bfloat162 bv = __float22bfloat162_rn(
                            make_float2(acc[mt * 7 + nt][h * 2], acc[mt * 7 + nt][h * 2 + 1]));
                        hout[(size_t)r * 32 + (c0 >> 1)] = *(unsigned*)&bv;
                    }
                }
            }
        }
    }
}

// ---------------- Aggregation 1 + fused lin2 (1 node per QUARTER-warp) -------
// 8 lanes per node; lane covers cols [8*l8, 8*l8+8) as one uint4 (8 bf16).
// lin2: smem transpose; lane jo (0..6) of each node computes output jo over
// all 64 cols. (champion form)
__global__ __launch_bounds__(256) void agg1_kernel(const float* __restrict__ b1,
                                                   const float* __restrict__ w2) {
    __shared__ float w2s[64 * OUTD];   // zero-extended rows 50..63
    __shared__ float o1s[32][68];      // row stride 68 -> bank-conflict-free
    int t = threadIdx.x;
    int hw = t >> 3;        // node slot 0..31
    int l8 = t & 7;
    for (int i = t; i < 64 * OUTD; i += 256)
        w2s[i] = (i < HID * OUTD) ? __ldg(&w2[i]) : 0.f;
    __syncthreads();
    int v = blockIdx.x * 32 + hw;   // grid 3125 * 32 = 100000 exactly
    int s0 = __ldg(&g_rowptr[v]);
    int s1 = __ldg(&g_rowptr[v + 1]);
    float dv = __ldg(&g_dinv[v]);
    const uint4* hb = (const uint4*)g_h1b;   // 8 uint4 per row

    float a[8] = {0.f, 0.f, 0.f, 0.f, 0.f, 0.f, 0.f, 0.f};
    uint4 su = __ldg(&hb[(size_t)v * 8 + l8]);
    acc_bf16x8(a, su, dv);

    int j = s0;
    for (; j + 3 < s1; j += 4) {
        int2 e0 = __ldg(&g_edge[j]);
        int2 e1 = __ldg(&g_edge[j + 1]);
        int2 e2 = __ldg(&g_edge[j + 2]);
        int2 e3 = __ldg(&g_edge[j + 3]);
        uint4 u0 = __ldg(&hb[(size_t)e0.x * 8 + l8]);
        uint4 u1 = __ldg(&hb[(size_t)e1.x * 8 + l8]);
        uint4 u2 = __ldg(&hb[(size_t)e2.x * 8 + l8]);
        uint4 u3 = __ldg(&hb[(size_t)e3.x * 8 + l8]);
        acc_bf16x8(a, u0, __int_as_float(e0.y));
        acc_bf16x8(a, u1, __int_as_float(e1.y));
        acc_bf16x8(a, u2, __int_as_float(e2.y));
        acc_bf16x8(a, u3, __int_as_float(e3.y));
    }
    for (; j < s1; j++) {
        int2 e = __ldg(&g_edge[j]);
        uint4 u = __ldg(&hb[(size_t)e.x * 8 + l8]);
        acc_bf16x8(a, u, __int_as_float(e.y));
    }

    // relu + b1 for the 8 covered cols; pad cols (f >= HID) forced to 0
    float o[8];
#pragma unroll
    for (int c = 0; c < 8; c++) {
        int f = 8 * l8 + c;
        o[c] = (f < HID) ? fmaxf(fmaf(dv, a[c], __ldg(&b1[f])), 0.f) : 0.f;
    }
    *(float4*)&o1s[hw][8 * l8]     = make_float4(o[0], o[1], o[2], o[3]);
    *(float4*)&o1s[hw][8 * l8 + 4] = make_float4(o[4], o[5], o[6], o[7]);
    __syncwarp();

    // reduction: lane jo (=l8) computes output jo over all 64 columns
    if (l8 < 7) {
        float p = 0.f;
#pragma unroll
        for (int f = 0; f < 64; f++)
            p = fmaf(o1s[hw][f], w2s[f * OUTD + l8], p);
        g_z[(size_t)v * 8 + l8] = p;
    }
}

// ---------------- Aggregation 2 (+b2, sigmoid; 8-lane champion form) ---------
__global__ __launch_bounds__(256) void agg2_kernel(const float* __restrict__ b2,
                                                   float* __restrict__ out) {
    int t = threadIdx.x;
    int jj = t & 7;
    int v = blockIdx.x * 32 + (t >> 3);
    int s0 = __ldg(&g_rowptr[v]);
    int s1 = __ldg(&g_rowptr[v + 1]);
    float dv = __ldg(&g_dinv[v]);
    float acc = dv * __ldg(&g_z[(size_t)v * 8 + jj]);
    int j = s0;
    for (; j + 3 < s1; j += 4) {
        int2 e0 = __ldg(&g_edge[j]);
        int2 e1 = __ldg(&g_edge[j + 1]);
        int2 e2 = __ldg(&g_edge[j + 2]);
        int2 e3 = __ldg(&g_edge[j + 3]);
        acc = fmaf(__int_as_float(e0.y), __ldg(&g_z[(size_t)e0.x * 8 + jj]), acc);
        acc = fmaf(__int_as_float(e1.y), __ldg(&g_z[(size_t)e1.x * 8 + jj]), acc);
        acc = fmaf(__int_as_float(e2.y), __ldg(&g_z[(size_t)e2.x * 8 + jj]), acc);
        acc = fmaf(__int_as_float(e3.y), __ldg(&g_z[(size_t)e3.x * 8 + jj]), acc);
    }
    for (; j < s1; j++) {
        int2 e = __ldg(&g_edge[j]);
        acc = fmaf(__int_as_float(e.y), __ldg(&g_z[(size_t)e.x * 8 + jj]), acc);
    }
    if (jj < OUTD) {
        float zz = fmaf(dv, acc, __ldg(&b2[jj]));
        out[v * OUTD + jj] = 1.f / (1.f + __expf(-zz));
    }
}

// ---------------- launch (two-stream fork/join for CSR || GEMM overlap) ------
struct AsyncRes {
    cudaStream_t s1;
    cudaEvent_t eFork, eJoin;
    AsyncRes() {
        cudaStreamCreateWithFlags(&s1, cudaStreamNonBlocking);
        cudaEventCreateWithFlags(&eFork, cudaEventDisableTiming);
        cudaEventCreateWithFlags(&eJoin, cudaEventDisableTiming);
    }
};

extern "C" void kernel_launch(void* const* d_in, const int* in_sizes, int n_in,
                              void* d_out, int out_size) {
    static AsyncRes ar;  // created on first (non-captured) correctness call

    const float* x  = (const float*)d_in[0];
    const int*   ei = (const int*)d_in[1];
    const float* w1 = (const float*)d_in[2];
    const float* b1 = (const float*)d_in[3];
    const float* w2 = (const float*)d_in[4];
    const float* b2 = (const float*)d_in[5];
    float* out = (float*)d_out;

    const int* row = ei;            // edge_index[0] = src
    const int* col = ei + NEDGES;   // edge_index[1] = dst

    // fork: CSR chain on s1, GEMM path on stream 0 — fully independent
    cudaEventRecord(ar.eFork, 0);
    cudaStreamWaitEvent(ar.s1, ar.eFork, 0);

    // stream 0: dense path
    w1pad_kernel<<<360, 256>>>(w1);
    gemm1_kernel<<<782, 128>>>(x);

    // stream s1: CSR build (hidden under gemm1)
    count_kernel<<<6250, 256, 0, ar.s1>>>(col);
    scan_local_kernel<<<98, 1024, 0, ar.s1>>>();      // also computes dinv
    scan_bsums_kernel<<<1, 128, 0, ar.s1>>>();
    scan_add_kernel<<<391, 256, 0, ar.s1>>>();        // also zeroes counts
    scatter_kernel<<<6250, 256, 0, ar.s1>>>(row, col);

    // join
    cudaEventRecord(ar.eJoin, ar.s1);
    cudaStreamWaitEvent(0, ar.eJoin, 0);

    // aggregations (need both paths)
    agg1_kernel<<<3125, 256>>>(b1, w2);               // fused lin2, 32 nodes/block
    agg2_kernel<<<3125, 256>>>(b2, out);
}